// round 8
// baseline (speedup 1.0000x reference)
#include <cuda_runtime.h>
#include <cuda_bf16.h>
#include <cstdint>
#include <cstring>

// Problem dims
#define BDIM 16384
#define KDIM 4096
#define NDIM 512

// Binarized weight, bf16 {0,1}, [NDIM, KDIM] row-major (K-contiguous). 4 MB.
__device__ __align__(256) __nv_bfloat16 g_wbin[(size_t)NDIM * KDIM];

// ---------------------------------------------------------------------------
// helpers
// ---------------------------------------------------------------------------
__device__ __forceinline__ uint32_t smem_u32(const void* p) {
    uint32_t a;
    asm("{ .reg .u64 t; cvta.to.shared.u64 t, %1; cvt.u32.u64 %0, t; }"
        : "=r"(a) : "l"(p));
    return a;
}

#define SWZ(off) ((uint32_t)(off) ^ ((((uint32_t)(off)) >> 3) & 0x70))

#define LDSM_X4(r0, r1, r2, r3, addr) \
    asm volatile("ldmatrix.sync.aligned.m8n8.x4.shared.b16 {%0,%1,%2,%3}, [%4];" \
        : "=r"(r0), "=r"(r1), "=r"(r2), "=r"(r3) : "r"(addr))

#define MMA16816(d, a, b0, b1) \
    asm volatile("mma.sync.aligned.m16n8k16.row.col.f32.bf16.bf16.f32 " \
        "{%0,%1,%2,%3}, {%4,%5,%6,%7}, {%8,%9}, {%0,%1,%2,%3};" \
        : "+f"((d)[0]), "+f"((d)[1]), "+f"((d)[2]), "+f"((d)[3]) \
        : "r"((a)[0]), "r"((a)[1]), "r"((a)[2]), "r"((a)[3]), "r"(b0), "r"(b1))

#define CP_ASYNC16(dst, src) \
    asm volatile("cp.async.cg.shared.global [%0], [%1], 16;" \
        :: "r"(dst), "l"(src) : "memory")
#define CP_COMMIT() asm volatile("cp.async.commit_group;" ::: "memory")
#define CP_WAIT2()  asm volatile("cp.async.wait_group 2;" ::: "memory")

#define STS128(addr, a, b, c, d) \
    asm volatile("st.shared.v4.b32 [%0], {%1, %2, %3, %4};" \
        :: "r"(addr), "r"(a), "r"(b), "r"(c), "r"(d) : "memory")

__device__ __forceinline__ uint32_t pack_bf16x2(float lo, float hi) {
    __nv_bfloat162 h = __floats2bfloat162_rn(lo, hi);
    uint32_t r;
    memcpy(&r, &h, 4);
    return r;
}

// ---------------------------------------------------------------------------
// Kernel 1: binarize weight -> bf16 {0,1}. Pure bit select, no float math.
// ---------------------------------------------------------------------------
__global__ void __launch_bounds__(256) binarize_kernel(
    const float* __restrict__ w, const float* __restrict__ u) {
    int i = blockIdx.x * 256 + threadIdx.x;   // 8 elems each
    const float4* w4 = reinterpret_cast<const float4*>(w) + (size_t)i * 2;
    const float4* u4 = reinterpret_cast<const float4*>(u) + (size_t)i * 2;
    float4 wa = w4[0], wb = w4[1];
    float4 ua = u4[0], ub = u4[1];
    // bf16(1.0f) = 0x3F80
    uint32_t o0 = (ua.x < wa.x ? 0x00003F80u : 0u) | (ua.y < wa.y ? 0x3F800000u : 0u);
    uint32_t o1 = (ua.z < wa.z ? 0x00003F80u : 0u) | (ua.w < wa.w ? 0x3F800000u : 0u);
    uint32_t o2 = (ub.x < wb.x ? 0x00003F80u : 0u) | (ub.y < wb.y ? 0x3F800000u : 0u);
    uint32_t o3 = (ub.z < wb.z ? 0x00003F80u : 0u) | (ub.w < wb.w ? 0x3F800000u : 0u);
    reinterpret_cast<uint4*>(g_wbin)[i] = make_uint4(o0, o1, o2, o3);
}

// ---------------------------------------------------------------------------
// Kernel 2: bf16 mma.sync GEMM with FUSED fp32->bf16 conversion of x.
//   out[16384, 512] = bf16(x[16384, 4096]) @ g_wbin[512, 4096]^T
//   BM=256, BN=128, BK=64. 256 threads = 8 warps (4 x 2), warp tile 64x64.
//   A path: LDG.128 fp32 (quarter-chunk, 2 rotating reg buffers, issued
//           2 ks-steps = ~1000cyc before use) -> cvt bf16 -> swizzled STS
//           into a 2-stage A smem buffer.
//   B path: cp.async, 4-stage ring (unchanged from R4).
//   (R8: removes the 60us standalone convert kernel; GEMM is at its legacy
//    HMMA ceiling so the extra LDG/CVT/STS ride the idle LSU/ALU pipes.)
// ---------------------------------------------------------------------------
static constexpr int BM = 256, BN = 128, BK = 64;
static constexpr int NC = KDIM / BK;              // 64
static constexpr int THREADS = 256;

static constexpr int A_ST  = BM * 128;            // 32 KB, x2 stages
static constexpr int B_ST  = BN * 128;            // 16 KB, x4 stages
static constexpr int B_OFF = 2 * A_ST;            // 64 KB
static constexpr int SMEM_TOTAL = B_OFF + 4 * B_ST;  // 128 KB

// cp.async the bf16 weight tile for chunk c into B ring stage.
__device__ __forceinline__ void cpB(uint32_t bbase, int c, int n0, int tid) {
    const __nv_bfloat16* bg = g_wbin + (size_t)n0 * KDIM + (size_t)c * BK;
    #pragma unroll
    for (int it = 0; it < 4; it++) {              // 1024 tasks: 128 rows x 8 segs
        const int task = tid + it * THREADS;
        const int r = task >> 3;
        const int t = task & 7;
        CP_ASYNC16(bbase + SWZ(r * 128 + t * 16),
                   bg + (size_t)r * KDIM + t * 8);
    }
}

// LDG one quarter (64 rows x 64 cols) of A chunk into a register buffer.
// Thread t: row q*64 + (t>>2), cols (t&3)*16 .. +15 (4x float4, coalesced).
__device__ __forceinline__ void ldgQ(const float* __restrict__ xg,
                                     int chunk, int q, int sr, int sc,
                                     float4 rb[4]) {
    const float4* p = reinterpret_cast<const float4*>(
        xg + (size_t)(q * 64 + sr) * KDIM + chunk * BK + sc);
    rb[0] = p[0]; rb[1] = p[1]; rb[2] = p[2]; rb[3] = p[3];
}

// Convert + store one quarter into the (swizzled) bf16 A smem tile.
__device__ __forceinline__ void stsQ(uint32_t abase, int q, int sr, int sc4,
                                     const float4 rb[4]) {
    uint32_t u[8];
    #pragma unroll
    for (int j = 0; j < 4; j++) {
        u[2 * j]     = pack_bf16x2(rb[j].x, rb[j].y);
        u[2 * j + 1] = pack_bf16x2(rb[j].z, rb[j].w);
    }
    const uint32_t base = (uint32_t)((q * 64 + sr) * 128 + sc4 * 32);
    STS128(abase + SWZ(base),      u[0], u[1], u[2], u[3]);
    STS128(abase + SWZ(base + 16), u[4], u[5], u[6], u[7]);
}

__global__ void __launch_bounds__(THREADS, 1) binlin_gemm(
    const float* __restrict__ x, float* __restrict__ out) {
    extern __shared__ char smem[];
    const uint32_t smem_base = smem_u32(smem);
    const int tid = threadIdx.x;
    const int wid = tid >> 5;
    const int lid = tid & 31;

    const int n0 = blockIdx.x * BN;               // 0..384 step 128
    const int m0 = blockIdx.y * BM;               // 0..16128 step 256
    const float* xg = x + (size_t)m0 * KDIM;

    const int warp_m = wid >> 1;                  // 0..3  (64 rows each)
    const int warp_n = wid & 1;                   // 0..1  (64 cols each)

    // A staging coords
    const int sr  = tid >> 2;                     // 0..63 row within quarter
    const int sc4 = tid & 3;                      // col group (x16 fp32)
    const int sc  = sc4 * 16;

    // per-lane ldmatrix address components
    const int lr = lid & 7;
    const int lg = lid >> 3;
    const int a_row  = warp_m * 64 + (lg & 1) * 8 + lr;   // + mf*16
    const int a_colb = (lg >> 1) * 16;                    // + ks*32
    const int b_row  = warp_n * 64 + (lg >> 1) * 8 + lr;  // + nf2*16
    const int b_colb = (lg & 1) * 16;                     // + ks*32

    float acc[4][8][4];
    #pragma unroll
    for (int i = 0; i < 4; i++)
        #pragma unroll
        for (int j = 0; j < 8; j++)
            #pragma unroll
            for (int k = 0; k < 4; k++) acc[i][j][k] = 0.f;

    float4 rb[2][4];   // two rotating quarter buffers (16 fp32 each)

    // ---- prologue ----
    // B: prefetch ring stages 0..2
    #pragma unroll
    for (int s = 0; s < 3; s++) {
        cpB(smem_base + B_OFF + s * B_ST, s, n0, tid);
        CP_COMMIT();
    }
    // A(0): load + convert + store all 4 quarters (latency exposed once, ~1us)
    {
        const uint32_t abase0 = smem_base;        // stage 0
        ldgQ(xg, 0, 0, sr, sc, rb[0]);
        ldgQ(xg, 0, 1, sr, sc, rb[1]);
        stsQ(abase0, 0, sr, sc4, rb[0]);
        ldgQ(xg, 0, 2, sr, sc, rb[0]);
        stsQ(abase0, 1, sr, sc4, rb[1]);
        ldgQ(xg, 0, 3, sr, sc, rb[1]);
        stsQ(abase0, 2, sr, sc4, rb[0]);
        stsQ(abase0, 3, sr, sc4, rb[1]);
    }
    // A(1): pre-issue quarters 0,1 (as-if ks2/ks3 of iteration -1)
    ldgQ(xg, 1, 0, sr, sc, rb[0]);
    ldgQ(xg, 1, 1, sr, sc, rb[1]);
    __syncthreads();   // A(0) visible to all warps

    // ---- main loop ----
    for (int c = 0; c < NC; c++) {
        CP_WAIT2();            // oldest B group (chunk c) complete
        __syncthreads();       // B(c) visible; B stage (c+3)&3 free; A stage flip safe

        if (c + 3 < NC)
            cpB(smem_base + B_OFF + ((c + 3) & 3) * B_ST, c + 3, n0, tid);
        CP_COMMIT();           // keep group count in lockstep (may be empty)

        const uint32_t abase  = smem_base + (c & 1) * A_ST;
        const uint32_t abaseN = smem_base + ((c + 1) & 1) * A_ST;
        const uint32_t bbase  = smem_base + B_OFF + (c & 3) * B_ST;

        #pragma unroll
        for (int ks = 0; ks < 4; ks++) {
            uint32_t a[4][4];
            #pragma unroll
            for (int mf = 0; mf < 4; mf++) {
                const uint32_t addr = abase +
                    SWZ((a_row + mf * 16) * 128 + ks * 32 + a_colb);
                LDSM_X4(a[mf][0], a[mf][1], a[mf][2], a[mf][3], addr);
            }
            uint32_t b[4][4];
            #pragma unroll
            for (int nf2 = 0; nf2 < 4; nf2++) {
                const uint32_t addr = bbase +
                    SWZ((b_row + nf2 * 16) * 128 + ks * 32 + b_colb);
                LDSM_X4(b[nf2][0], b[nf2][1], b[nf2][2], b[nf2][3], addr);
            }

            // A producer: STS quarter ks of A(c+1) (loaded 2 ks earlier),
            // then refill the buffer with the next quarter per schedule:
            //   ks<2 -> quarter ks+2 of A(c+1); ks>=2 -> quarter ks-2 of A(c+2)
            const int buf = ks & 1;
            if (c + 1 < NC)
                stsQ(abaseN, ks, sr, sc4, rb[buf]);
            {
                const int lq = (ks + 2) & 3;
                const int lc = c + 1 + (ks >> 1);
                if (lc < NC)
                    ldgQ(xg, lc, lq, sr, sc, rb[buf]);
            }

            #pragma unroll
            for (int mf = 0; mf < 4; mf++) {
                #pragma unroll
                for (int nf = 0; nf < 8; nf++) {
                    MMA16816(acc[mf][nf], a[mf],
                             b[nf >> 1][(nf & 1) * 2 + 0],
                             b[nf >> 1][(nf & 1) * 2 + 1]);
                }
            }
        }
    }

    // ---- epilogue: fragments -> gmem ----
    const int er = lid >> 2;          // 0..7
    const int ec = (lid & 3) * 2;     // 0,2,4,6
    #pragma unroll
    for (int mf = 0; mf < 4; mf++) {
        #pragma unroll
        for (int nf = 0; nf < 8; nf++) {
            const int m = m0 + warp_m * 64 + mf * 16 + er;
            const int n = n0 + warp_n * 64 + nf * 8 + ec;
            float2 v0 = make_float2(acc[mf][nf][0], acc[mf][nf][1]);
            float2 v1 = make_float2(acc[mf][nf][2], acc[mf][nf][3]);
            *reinterpret_cast<float2*>(out + (size_t)m * NDIM + n)       = v0;
            *reinterpret_cast<float2*>(out + (size_t)(m + 8) * NDIM + n) = v1;
        }
    }
}

// ---------------------------------------------------------------------------
// Launch
// ---------------------------------------------------------------------------
extern "C" void kernel_launch(void* const* d_in, const int* in_sizes, int n_in,
                              void* d_out, int out_size) {
    const float* x = (const float*)d_in[0];   // [16384, 4096]
    const float* w = (const float*)d_in[1];   // [512, 4096] bernoulli probs
    const float* u = (const float*)d_in[2];   // [512, 4096] uniform sample
    float* out = (float*)d_out;               // [16384, 512]

    cudaFuncSetAttribute(binlin_gemm,
                         cudaFuncAttributeMaxDynamicSharedMemorySize, SMEM_TOTAL);

    binarize_kernel<<<(NDIM * KDIM) / (256 * 8), 256>>>(w, u);
    dim3 grid(NDIM / BN, BDIM / BM);          // (4, 64) = 256 CTAs
    binlin_gemm<<<grid, THREADS, SMEM_TOTAL>>>(x, out);
}

// round 9
// speedup vs baseline: 1.2031x; 1.2031x over previous
#include <cuda_runtime.h>
#include <cuda_bf16.h>
#include <cstdint>
#include <cstring>

// Problem dims
#define BDIM 16384
#define KDIM 4096
#define NDIM 512

// Binarized weight, bf16 {0,1}, [NDIM, KDIM] row-major (K-contiguous). 4 MB.
__device__ __align__(256) __nv_bfloat16 g_wbin[(size_t)NDIM * KDIM];
// Pre-converted x, bf16, [BDIM, KDIM]. 128 MB.
__device__ __align__(256) __nv_bfloat16 g_xbf[(size_t)BDIM * KDIM];

// ---------------------------------------------------------------------------
// helpers
// ---------------------------------------------------------------------------
__device__ __forceinline__ uint32_t smem_u32(const void* p) {
    uint32_t a;
    asm("{ .reg .u64 t; cvta.to.shared.u64 t, %1; cvt.u32.u64 %0, t; }"
        : "=r"(a) : "l"(p));
    return a;
}

#define SWZ(off) ((uint32_t)(off) ^ ((((uint32_t)(off)) >> 3) & 0x70))

#define LDSM_X4(r0, r1, r2, r3, addr) \
    asm volatile("ldmatrix.sync.aligned.m8n8.x4.shared.b16 {%0,%1,%2,%3}, [%4];" \
        : "=r"(r0), "=r"(r1), "=r"(r2), "=r"(r3) : "r"(addr))

#define MMA16816(d, a, b0, b1) \
    asm volatile("mma.sync.aligned.m16n8k16.row.col.f32.bf16.bf16.f32 " \
        "{%0,%1,%2,%3}, {%4,%5,%6,%7}, {%8,%9}, {%0,%1,%2,%3};" \
        : "+f"((d)[0]), "+f"((d)[1]), "+f"((d)[2]), "+f"((d)[3]) \
        : "r"((a)[0]), "r"((a)[1]), "r"((a)[2]), "r"((a)[3]), "r"(b0), "r"(b1))

#define CP_ASYNC16(dst, src) \
    asm volatile("cp.async.cg.shared.global [%0], [%1], 16;" \
        :: "r"(dst), "l"(src) : "memory")
#define CP_COMMIT() asm volatile("cp.async.commit_group;" ::: "memory")
#define CP_WAIT1()  asm volatile("cp.async.wait_group 1;" ::: "memory")

__device__ __forceinline__ uint32_t pack_bf16x2(float lo, float hi) {
    __nv_bfloat162 h = __floats2bfloat162_rn(lo, hi);
    uint32_t r;
    memcpy(&r, &h, 4);
    return r;
}

// ---------------------------------------------------------------------------
// Kernel 1: binarize weight -> bf16 {0,1}. Pure bit select, no float math.
// ---------------------------------------------------------------------------
__global__ void __launch_bounds__(256) binarize_kernel(
    const float* __restrict__ w, const float* __restrict__ u) {
    int i = blockIdx.x * 256 + threadIdx.x;   // 8 elems each
    const float4* w4 = reinterpret_cast<const float4*>(w) + (size_t)i * 2;
    const float4* u4 = reinterpret_cast<const float4*>(u) + (size_t)i * 2;
    float4 wa = w4[0], wb = w4[1];
    float4 ua = u4[0], ub = u4[1];
    // bf16(1.0f) = 0x3F80
    uint32_t o0 = (ua.x < wa.x ? 0x00003F80u : 0u) | (ua.y < wa.y ? 0x3F800000u : 0u);
    uint32_t o1 = (ua.z < wa.z ? 0x00003F80u : 0u) | (ua.w < wa.w ? 0x3F800000u : 0u);
    uint32_t o2 = (ub.x < wb.x ? 0x00003F80u : 0u) | (ub.y < wb.y ? 0x3F800000u : 0u);
    uint32_t o3 = (ub.z < wb.z ? 0x00003F80u : 0u) | (ub.w < wb.w ? 0x3F800000u : 0u);
    reinterpret_cast<uint4*>(g_wbin)[i] = make_uint4(o0, o1, o2, o3);
}

// ---------------------------------------------------------------------------
// Kernel 2: convert x fp32 -> bf16 (streaming, DRAM-bound ~60us).
// (R8 showed fusing this into the GEMM costs more than it saves: regs=255
//  spills + L1 67.7% -> tensor 40%. Keep it split.)
// ---------------------------------------------------------------------------
__global__ void __launch_bounds__(256) convert_x_kernel(const float* __restrict__ x) {
    int i = blockIdx.x * 256 + threadIdx.x;   // 8 elems each
    const float4* p = reinterpret_cast<const float4*>(x) + (size_t)i * 2;
    float4 f0 = p[0], f1 = p[1];
    uint4 o;
    o.x = pack_bf16x2(f0.x, f0.y);
    o.y = pack_bf16x2(f0.z, f0.w);
    o.z = pack_bf16x2(f1.x, f1.y);
    o.w = pack_bf16x2(f1.z, f1.w);
    reinterpret_cast<uint4*>(g_xbf)[i] = o;
}

// ---------------------------------------------------------------------------
// Kernel 3: bf16 mma.sync GEMM, all-cp.async, 3-stage pipeline, 2 CTAs/SM.
//   out[16384, 512] = g_xbf[16384, 4096] @ g_wbin[512, 4096]^T
//   BM=128, BN=128, BK=64. 256 threads = 8 warps (4m x 2n), warp tile 32x64.
//   acc = 64 regs -> fits 128-reg cap -> 2 co-resident CTAs per SM whose
//   independent barriers keep the tensor pipe fed through each other's
//   cp.async waits / syncs (R4 ran 1 CTA/SM at tensor=68%).
// ---------------------------------------------------------------------------
static constexpr int BM = 128, BN = 128, BK = 64;
static constexpr int NC = KDIM / BK;              // 64
static constexpr int THREADS = 256;
static constexpr int STAGES = 3;

static constexpr int A_ST  = BM * 128;            // 16 KB
static constexpr int B_ST  = BN * 128;            // 16 KB
static constexpr int STAGE = A_ST + B_ST;         // 32 KB
static constexpr int SMEM_TOTAL = STAGES * STAGE; // 96 KB  (x2 CTAs = 192 KB/SM)

// cp.async both tiles for chunk c into stage buffer.
__device__ __forceinline__ void cpAB(uint32_t sbase, int c, int m0, int n0, int tid) {
    const __nv_bfloat16* ag = g_xbf + (size_t)m0 * KDIM + (size_t)c * BK;
    #pragma unroll
    for (int it = 0; it < 4; it++) {              // 1024 tasks: 128 rows x 8 segs
        const int task = tid + it * THREADS;
        const int r = task >> 3;
        const int t = task & 7;
        CP_ASYNC16(sbase + SWZ(r * 128 + t * 16),
                   ag + (size_t)r * KDIM + t * 8);
    }
    const __nv_bfloat16* bg = g_wbin + (size_t)n0 * KDIM + (size_t)c * BK;
    const uint32_t bbase = sbase + A_ST;
    #pragma unroll
    for (int it = 0; it < 4; it++) {              // 1024 tasks: 128 rows x 8 segs
        const int task = tid + it * THREADS;
        const int r = task >> 3;
        const int t = task & 7;
        CP_ASYNC16(bbase + SWZ(r * 128 + t * 16),
                   bg + (size_t)r * KDIM + t * 8);
    }
}

__global__ void __launch_bounds__(THREADS, 2) binlin_gemm(float* __restrict__ out) {
    extern __shared__ char smem[];
    const uint32_t smem_base = smem_u32(smem);
    const int tid = threadIdx.x;
    const int wid = tid >> 5;
    const int lid = tid & 31;

    const int n0 = blockIdx.x * BN;               // 0..384 step 128
    const int m0 = blockIdx.y * BM;               // 0..16256 step 128

    const int warp_m = wid & 3;                   // 0..3  (32 rows each)
    const int warp_n = wid >> 2;                  // 0..1  (64 cols each)

    // per-lane ldmatrix address components
    const int lr = lid & 7;
    const int lg = lid >> 3;
    const int a_row  = warp_m * 32 + (lg & 1) * 8 + lr;   // + mf*16
    const int a_colb = (lg >> 1) * 16;                    // + ks*32
    const int b_row  = warp_n * 64 + (lg >> 1) * 8 + lr;  // + nf2*16
    const int b_colb = (lg & 1) * 16;                     // + ks*32

    float acc[2][8][4];
    #pragma unroll
    for (int i = 0; i < 2; i++)
        #pragma unroll
        for (int j = 0; j < 8; j++)
            #pragma unroll
            for (int k = 0; k < 4; k++) acc[i][j][k] = 0.f;

    // ---- prologue: prefetch stages 0..1 ----
    #pragma unroll
    for (int s = 0; s < STAGES - 1; s++) {
        cpAB(smem_base + s * STAGE, s, m0, n0, tid);
        CP_COMMIT();
    }

    // ---- main loop ----
    int stage_c = 0;                              // (c % 3) without division
    for (int c = 0; c < NC; c++) {
        CP_WAIT1();            // <=1 group pending -> chunk c landed
        __syncthreads();       // visibility + prior readers of reused stage done

        if (c + STAGES - 1 < NC) {
            int stage_w = stage_c + (STAGES - 1);
            if (stage_w >= STAGES) stage_w -= STAGES;
            cpAB(smem_base + stage_w * STAGE, c + STAGES - 1, m0, n0, tid);
        }
        CP_COMMIT();           // keep group count in lockstep (may be empty)

        const uint32_t abase = smem_base + stage_c * STAGE;
        const uint32_t bbase = abase + A_ST;
        if (++stage_c == STAGES) stage_c = 0;

        #pragma unroll
        for (int ks = 0; ks < 4; ks++) {
            uint32_t a[2][4];
            #pragma unroll
            for (int mf = 0; mf < 2; mf++) {
                const uint32_t addr = abase +
                    SWZ((a_row + mf * 16) * 128 + ks * 32 + a_colb);
                LDSM_X4(a[mf][0], a[mf][1], a[mf][2], a[mf][3], addr);
            }
            uint32_t b[4][4];
            #pragma unroll
            for (int nf2 = 0; nf2 < 4; nf2++) {
                const uint32_t addr = bbase +
                    SWZ((b_row + nf2 * 16) * 128 + ks * 32 + b_colb);
                LDSM_X4(b[nf2][0], b[nf2][1], b[nf2][2], b[nf2][3], addr);
            }
            #pragma unroll
            for (int mf = 0; mf < 2; mf++) {
                #pragma unroll
                for (int nf = 0; nf < 8; nf++) {
                    MMA16816(acc[mf][nf], a[mf],
                             b[nf >> 1][(nf & 1) * 2 + 0],
                             b[nf >> 1][(nf & 1) * 2 + 1]);
                }
            }
        }
    }

    // ---- epilogue: fragments -> gmem ----
    const int er = lid >> 2;          // 0..7
    const int ec = (lid & 3) * 2;     // 0,2,4,6
    #pragma unroll
    for (int mf = 0; mf < 2; mf++) {
        #pragma unroll
        for (int nf = 0; nf < 8; nf++) {
            const int m = m0 + warp_m * 32 + mf * 16 + er;
            const int n = n0 + warp_n * 64 + nf * 8 + ec;
            float2 v0 = make_float2(acc[mf][nf][0], acc[mf][nf][1]);
            float2 v1 = make_float2(acc[mf][nf][2], acc[mf][nf][3]);
            *reinterpret_cast<float2*>(out + (size_t)m * NDIM + n)       = v0;
            *reinterpret_cast<float2*>(out + (size_t)(m + 8) * NDIM + n) = v1;
        }
    }
}

// ---------------------------------------------------------------------------
// Launch
// ---------------------------------------------------------------------------
extern "C" void kernel_launch(void* const* d_in, const int* in_sizes, int n_in,
                              void* d_out, int out_size) {
    const float* x = (const float*)d_in[0];   // [16384, 4096]
    const float* w = (const float*)d_in[1];   // [512, 4096] bernoulli probs
    const float* u = (const float*)d_in[2];   // [512, 4096] uniform sample
    float* out = (float*)d_out;               // [16384, 512]

    cudaFuncSetAttribute(binlin_gemm,
                         cudaFuncAttributeMaxDynamicSharedMemorySize, SMEM_TOTAL);

    binarize_kernel<<<(NDIM * KDIM) / (256 * 8), 256>>>(w, u);
    convert_x_kernel<<<((size_t)BDIM * KDIM) / (256 * 8), 256>>>(x);
    dim3 grid(NDIM / BN, BDIM / BM);          // (4, 128) = 512 CTAs, 2/SM
    binlin_gemm<<<grid, THREADS, SMEM_TOTAL>>>(out);
}